// round 17
// baseline (speedup 1.0000x reference)
#include <cuda_runtime.h>
#include <cuda_bf16.h>
#include <cstdint>
#include <string.h>
#include <math.h>

typedef __nv_bfloat16 bf16;

#define B_ 8
#define C_ 512
#define N_ 2048
#define CH_ 256

// ---- device-global scratch ----
__device__ bf16     g_xt [B_ * N_ * C_];             // [n][c] bf16
__device__ bf16     g_Wqk[2 * CH_ * C_];             // rows 0-255 Wq, 256-511 Wk
__device__ bf16     g_Wv [C_ * C_];
__device__ float    g_bqk[2 * CH_];                  // packed bq|bk
__device__ bf16     g_QK [B_ * N_ * C_];             // [n][0..255]=Q, [256..511]=K
__device__ bf16     g_V  [B_ * C_ * N_];             // [c][m]
__device__ bf16     g_E  [(size_t)B_ * N_ * N_];     // [n][m] exp(logit)
__device__ float    g_rowsum[B_ * N_];               // per-row exp sums
__device__ unsigned g_cnt_w;                         // weights+bias done (513)
__device__ unsigned g_cnt_x[B_];                     // transpose tiles done (1024/b)
__device__ unsigned g_cntQK[B_ * 16];                // QK proj done per (b, n-blk)
__device__ unsigned g_cntV [B_ * 4];                 // V proj done per (b, c-blk)
__device__ unsigned g_cntS [B_ * 16];                // scores done per (b, n-blk)
__device__ unsigned g_cnt_done;                      // AV CTAs done (512)

// ===========================================================================
// PTX helpers
// ===========================================================================
__device__ __forceinline__ uint32_t smem_u32(const void* p) {
    uint32_t a;
    asm("{ .reg .u64 t; cvta.to.shared.u64 t, %1; cvt.u32.u64 %0, t; }"
        : "=r"(a) : "l"(p));
    return a;
}
__device__ __forceinline__ void cp_async16(uint32_t dst, const void* src) {
    asm volatile("cp.async.cg.shared.global [%0], [%1], 16;\n" :: "r"(dst), "l"(src));
}
__device__ __forceinline__ void cp_commit() {
    asm volatile("cp.async.commit_group;\n");
}
template<int NW> __device__ __forceinline__ void cp_wait() {
    asm volatile("cp.async.wait_group %0;\n" :: "n"(NW));
}
__device__ __forceinline__ void ldsm4(uint32_t* r, uint32_t addr) {
    asm volatile("ldmatrix.sync.aligned.m8n8.x4.shared.b16 {%0,%1,%2,%3}, [%4];\n"
                 : "=r"(r[0]), "=r"(r[1]), "=r"(r[2]), "=r"(r[3]) : "r"(addr));
}
__device__ __forceinline__ void mma16816(float* c, const uint32_t* a,
                                         uint32_t b0, uint32_t b1) {
    asm volatile(
        "mma.sync.aligned.m16n8k16.row.col.f32.bf16.bf16.f32 "
        "{%0,%1,%2,%3}, {%4,%5,%6,%7}, {%8,%9}, {%0,%1,%2,%3};\n"
        : "+f"(c[0]), "+f"(c[1]), "+f"(c[2]), "+f"(c[3])
        : "r"(a[0]), "r"(a[1]), "r"(a[2]), "r"(a[3]), "r"(b0), "r"(b1));
}
__device__ __forceinline__ unsigned ld_acquire(const unsigned* p) {
    unsigned v;
    asm volatile("ld.acquire.gpu.u32 %0, [%1];" : "=r"(v) : "l"(p));
    return v;
}
__device__ __forceinline__ void wait_cnt(const unsigned* p, unsigned target) {
    while (ld_acquire(p) < target) __nanosleep(64);
}

#define NSTG 3
#define SMEMB (NSTG * 32768)

// ===========================================================================
// Shared 128x128 K-major mainloop: acc[i][j] += sum_k A[i0+i,k]*B[j0+j,k]
// ===========================================================================
__device__ __forceinline__ void gemm_main(
    const bf16* __restrict__ Ab, const bf16* __restrict__ Bb,
    int lda, int ldb, int i0, int j0, int T,
    uint32_t s0, int tid, int wm, int wn,
    int rAl, int aHalf, int rBl, int bHalf,
    float acc[4][8][4])
{
    auto load_stage = [&](int t) {
        const uint32_t base = s0 + (uint32_t)(t % NSTG) * 32768u;
        const int k0 = t * 64;
        #pragma unroll
        for (int it = 0; it < 16; it++) {
            int q = it * 128 + tid;
            int qq = q & 1023;
            int row = qq >> 3, c = qq & 7;
            uint32_t dst = base + (q < 1024 ? 0u : 16384u)
                         + (uint32_t)(row * 128 + ((c ^ (row & 7)) << 4));
            const bf16* src = (q < 1024)
                ? Ab + (size_t)(i0 + row) * lda + k0 + c * 8
                : Bb + (size_t)(j0 + row) * ldb + k0 + c * 8;
            cp_async16(dst, src);
        }
        cp_commit();
    };

    load_stage(0);
    if (T > 1) load_stage(1); else cp_commit();

    for (int t = 0; t < T; t++) {
        if (t + 2 < T) load_stage(t + 2); else cp_commit();
        cp_wait<2>();
        __syncthreads();

        const uint32_t sa = s0 + (uint32_t)(t % NSTG) * 32768u;
        const uint32_t sb = sa + 16384u;
        #pragma unroll
        for (int k16 = 0; k16 < 4; k16++) {
            uint32_t a[4][4], b[4][4];
            #pragma unroll
            for (int mi = 0; mi < 4; mi++) {
                int row = wm + mi * 16 + rAl;
                int ch = 2 * k16 + aHalf;
                ldsm4(a[mi], sa + (uint32_t)(row * 128 + ((ch ^ (row & 7)) << 4)));
            }
            #pragma unroll
            for (int nh = 0; nh < 4; nh++) {
                int row = wn + nh * 16 + rBl;
                int ch = 2 * k16 + bHalf;
                ldsm4(b[nh], sb + (uint32_t)(row * 128 + ((ch ^ (row & 7)) << 4)));
            }
            #pragma unroll
            for (int mi = 0; mi < 4; mi++)
                #pragma unroll
                for (int ni = 0; ni < 8; ni++)
                    mma16816(acc[mi][ni], a[mi],
                             b[ni >> 1][(ni & 1) * 2], b[ni >> 1][(ni & 1) * 2 + 1]);
        }
        __syncthreads();
    }
}

// ===========================================================================
// Single-launch megakernel. Grid = 12290 CTAs, in dependency (bid) order:
//   [0, 512)        : weight fp32->bf16 conversion     -> cnt_w
//   512             : bias pack                         -> cnt_w   (target 513)
//   [513, 8705)     : x transpose tiles (batch-major)   -> cnt_x[b] (target 1024)
//   [8705, 9729)    : projections (gated cnt_w, cnt_x)  -> cntQK / cntV
//   [9729, 11777)   : scores + exp + rowsum (gated)     -> cntS
//   [11777, 12289)  : AV + normalize + residual (gated) -> cnt_done
//   12289           : reset CTA: waits cnt_done==512, zeroes all counters+rowsum
// Dispatch is in bid order; every gate waits only on strictly earlier bids.
// Reset is safe: cnt_done==512 implies every other CTA has exited.
// ===========================================================================
__global__ void __launch_bounds__(128, 2)
megakernel(const float* __restrict__ x,
           const float* __restrict__ Wq, const float* __restrict__ bq,
           const float* __restrict__ Wk, const float* __restrict__ bk,
           const float* __restrict__ Wv, const float* __restrict__ bv,
           float* __restrict__ out)
{
    extern __shared__ char smem[];
    const uint32_t s0 = smem_u32(smem);
    const int tid = threadIdx.x, warp = tid >> 5, lane = tid & 31;
    const int wm = (warp >> 1) * 64;
    const int wn = (warp & 1) * 64;
    const int rAl = lane & 15;
    const int aHalf = lane >> 4;
    const int rBl = (lane & 7) + ((lane & 16) >> 1);
    const int bHalf = (lane >> 3) & 1;
    const int er = lane >> 2;
    const int ec = 2 * (lane & 3);
    const int bid = blockIdx.x;

    const size_t sXT = (size_t)N_ * C_;
    const size_t sX  = (size_t)C_ * N_;
    const size_t sS  = (size_t)N_ * N_;

    if (bid < 512) {
        // ---------------- weight conversion ----------------
        const float4* src;
        __nv_bfloat162* dst;
        int base;
        if (bid < 128)      { src = (const float4*)Wq; dst = (__nv_bfloat162*)g_Wqk;
                              base = bid * 256; }
        else if (bid < 256) { src = (const float4*)Wk;
                              dst = (__nv_bfloat162*)(g_Wqk + CH_ * C_);
                              base = (bid - 128) * 256; }
        else                { src = (const float4*)Wv; dst = (__nv_bfloat162*)g_Wv;
                              base = (bid - 256) * 256; }
        #pragma unroll
        for (int r = 0; r < 2; r++) {
            int idx = base + tid + r * 128;
            float4 v = src[idx];
            dst[2 * idx]     = __float22bfloat162_rn(make_float2(v.x, v.y));
            dst[2 * idx + 1] = __float22bfloat162_rn(make_float2(v.z, v.w));
        }
        __syncthreads();
        __threadfence();
        if (tid == 0) atomicAdd(&g_cnt_w, 1u);
    } else if (bid == 512) {
        // ---------------- bias pack ----------------
        #pragma unroll
        for (int i = 0; i < 2; i++) {
            g_bqk[tid + i * 128]        = bq[tid + i * 128];
            g_bqk[CH_ + tid + i * 128]  = bk[tid + i * 128];
        }
        __syncthreads();
        __threadfence();
        if (tid == 0) atomicAdd(&g_cnt_w, 1u);
    } else if (bid < 8705) {
        // ---------------- x transpose tile (32x32) ----------------
        float (*tile)[33] = (float (*)[33])smem;
        int t = bid - 513;
        int bx = t & 63;            // n tile
        int by = (t >> 6) & 15;     // c tile
        int bz = t >> 10;           // batch (batch-major ordering)
        const int c0 = by * 32, n0 = bx * 32;
        const float* xb = x + (size_t)bz * sX;
        bf16* xtb = g_xt + (size_t)bz * sXT;
        const int tx = tid & 31, ty = tid >> 5;   // ty in [0,4)
        #pragma unroll
        for (int i = 0; i < 8; i++)
            tile[ty + 4 * i][tx] = xb[(size_t)(c0 + ty + 4 * i) * N_ + n0 + tx];
        __syncthreads();
        #pragma unroll
        for (int i = 0; i < 8; i++)
            xtb[(size_t)(n0 + ty + 4 * i) * C_ + c0 + tx] =
                __float2bfloat16(tile[tx][ty + 4 * i]);
        __syncthreads();
        __threadfence();
        if (tid == 0) atomicAdd(&g_cnt_x[bz], 1u);
    } else if (bid < 9729) {
        // ---------------- projections ----------------
        float acc[4][8][4];
        #pragma unroll
        for (int mi = 0; mi < 4; mi++)
            #pragma unroll
            for (int ni = 0; ni < 8; ni++)
                #pragma unroll
                for (int e = 0; e < 4; e++) acc[mi][ni][e] = 0.0f;

        const int pt = bid - 8705;
        const int b = pt >> 7, t = pt & 127;
        const bool isV = t >= 64;

        if (tid == 0) {
            wait_cnt(&g_cnt_w, 513u);
            wait_cnt(&g_cnt_x[b], 1024u);
        }
        __syncthreads();

        int i0, j0, lda, ldb;
        const bf16 *Ab, *Bb;
        if (!isV) {
            i0 = (t >> 2) * 128; j0 = (t & 3) * 128;
            Ab = g_xt + sXT * b; lda = C_;
            Bb = g_Wqk;          ldb = C_;
        } else {
            int tt = t - 64;
            i0 = (tt >> 4) * 128; j0 = (tt & 15) * 128;
            Ab = g_Wv;           lda = C_;
            Bb = g_xt + sXT * b; ldb = C_;
        }
        gemm_main(Ab, Bb, lda, ldb, i0, j0, C_ >> 6, s0, tid,
                  wm, wn, rAl, aHalf, rBl, bHalf, acc);

        if (!isV) {
            bf16* D = g_QK + sXT * b;
            #pragma unroll
            for (int mi = 0; mi < 4; mi++)
                #pragma unroll
                for (int ni = 0; ni < 8; ni++) {
                    const float* a4 = acc[mi][ni];
                    int gm = i0 + wm + mi * 16 + er;
                    int gn = j0 + wn + ni * 8 + ec;
                    float b0 = g_bqk[gn], b1 = g_bqk[gn + 1];
                    *(__nv_bfloat162*)&D[(size_t)gm * C_ + gn] =
                        __float22bfloat162_rn(make_float2(a4[0] + b0, a4[1] + b1));
                    *(__nv_bfloat162*)&D[(size_t)(gm + 8) * C_ + gn] =
                        __float22bfloat162_rn(make_float2(a4[2] + b0, a4[3] + b1));
                }
            __syncthreads();
            __threadfence();
            if (tid == 0) atomicAdd(&g_cntQK[b * 16 + (t >> 2)], 1u);
        } else {
            bf16* D = g_V + sX * b;
            #pragma unroll
            for (int mi = 0; mi < 4; mi++)
                #pragma unroll
                for (int ni = 0; ni < 8; ni++) {
                    const float* a4 = acc[mi][ni];
                    int gm = i0 + wm + mi * 16 + er;
                    int gn = j0 + wn + ni * 8 + ec;
                    float bb0 = bv[gm], bb1 = bv[gm + 8];
                    *(__nv_bfloat162*)&D[(size_t)gm * N_ + gn] =
                        __float22bfloat162_rn(make_float2(a4[0] + bb0, a4[1] + bb0));
                    *(__nv_bfloat162*)&D[(size_t)(gm + 8) * N_ + gn] =
                        __float22bfloat162_rn(make_float2(a4[2] + bb1, a4[3] + bb1));
                }
            __syncthreads();
            __threadfence();
            if (tid == 0) atomicAdd(&g_cntV[b * 4 + ((t - 64) >> 4)], 1u);
        }
    } else if (bid < 11777) {
        // ---------------- scores + exp + rowsum ----------------
        float acc[4][8][4];
        #pragma unroll
        for (int mi = 0; mi < 4; mi++)
            #pragma unroll
            for (int ni = 0; ni < 8; ni++)
                #pragma unroll
                for (int e = 0; e < 4; e++) acc[mi][ni][e] = 0.0f;

        const int s = bid - 9729;
        const int b = s >> 8, r = s & 255;
        const int ix = r & 15, iy = r >> 4;
        const int i0 = iy * 128, j0 = ix * 128;

        if (tid == 0) {
            wait_cnt(&g_cntQK[b * 16 + iy], 4u);
            wait_cnt(&g_cntQK[b * 16 + ix], 4u);
        }
        __syncthreads();

        gemm_main(g_QK + sXT * b, g_QK + sXT * b + CH_, C_, C_, i0, j0,
                  CH_ >> 6, s0, tid, wm, wn, rAl, aHalf, rBl, bHalf, acc);

        bf16* D = g_E + sS * b;
        float* rsb = g_rowsum + (size_t)b * N_;
        #pragma unroll
        for (int mi = 0; mi < 4; mi++) {
            float rs0 = 0.0f, rs1 = 0.0f;
            int gm = i0 + wm + mi * 16 + er;
            #pragma unroll
            for (int ni = 0; ni < 8; ni++) {
                const float* a4 = acc[mi][ni];
                int gn = j0 + wn + ni * 8 + ec;
                float e00 = __expf(a4[0] * 0.0625f);
                float e01 = __expf(a4[1] * 0.0625f);
                float e10 = __expf(a4[2] * 0.0625f);
                float e11 = __expf(a4[3] * 0.0625f);
                *(__nv_bfloat162*)&D[(size_t)gm * N_ + gn] =
                    __float22bfloat162_rn(make_float2(e00, e01));
                *(__nv_bfloat162*)&D[(size_t)(gm + 8) * N_ + gn] =
                    __float22bfloat162_rn(make_float2(e10, e11));
                rs0 += e00 + e01;
                rs1 += e10 + e11;
            }
            rs0 += __shfl_xor_sync(0xFFFFFFFFu, rs0, 1);
            rs0 += __shfl_xor_sync(0xFFFFFFFFu, rs0, 2);
            rs1 += __shfl_xor_sync(0xFFFFFFFFu, rs1, 1);
            rs1 += __shfl_xor_sync(0xFFFFFFFFu, rs1, 2);
            if ((lane & 3) == 0) {
                atomicAdd(&rsb[gm], rs0);
                atomicAdd(&rsb[gm + 8], rs1);
            }
        }
        __syncthreads();
        __threadfence();
        if (tid == 0) atomicAdd(&g_cntS[b * 16 + iy], 1u);
    } else if (bid < 12289) {
        // ---------------- AV + normalize + residual ----------------
        float acc[4][8][4];
        #pragma unroll
        for (int mi = 0; mi < 4; mi++)
            #pragma unroll
            for (int ni = 0; ni < 8; ni++)
                #pragma unroll
                for (int e = 0; e < 4; e++) acc[mi][ni][e] = 0.0f;

        const int s = bid - 11777;
        const int b = s >> 6, r = s & 63;
        const int jx = r & 15, cy = r >> 4;
        const int i0 = cy * 128, j0 = jx * 128;

        if (tid == 0) {
            wait_cnt(&g_cntS[b * 16 + jx], 16u);
            wait_cnt(&g_cntV[b * 4 + cy], 16u);
        }
        __syncthreads();

        gemm_main(g_V + sX * b, g_E + sS * b, N_, N_, i0, j0,
                  N_ >> 6, s0, tid, wm, wn, rAl, aHalf, rBl, bHalf, acc);

        float* D = out + sX * b;
        const float* R = x + sX * b;
        const float* rsb = g_rowsum + (size_t)b * N_;
        float inv[8][2];
        #pragma unroll
        for (int ni = 0; ni < 8; ni++) {
            int gn = j0 + wn + ni * 8 + ec;
            inv[ni][0] = 1.0f / rsb[gn];
            inv[ni][1] = 1.0f / rsb[gn + 1];
        }
        #pragma unroll
        for (int mi = 0; mi < 4; mi++)
            #pragma unroll
            for (int ni = 0; ni < 8; ni++) {
                const float* a4 = acc[mi][ni];
                int gm = i0 + wm + mi * 16 + er;
                int gn = j0 + wn + ni * 8 + ec;
                float2 r0 = *(const float2*)&R[(size_t)gm * N_ + gn];
                float2 r1 = *(const float2*)&R[(size_t)(gm + 8) * N_ + gn];
                *(float2*)&D[(size_t)gm * N_ + gn] =
                    make_float2(r0.x + a4[0] * inv[ni][0], r0.y + a4[1] * inv[ni][1]);
                *(float2*)&D[(size_t)(gm + 8) * N_ + gn] =
                    make_float2(r1.x + a4[2] * inv[ni][0], r1.y + a4[3] * inv[ni][1]);
            }
        __syncthreads();
        __threadfence();
        if (tid == 0) atomicAdd(&g_cnt_done, 1u);
    } else {
        // ---------------- reset CTA (last bid) ----------------
        if (tid == 0) wait_cnt(&g_cnt_done, 512u);
        __syncthreads();
        // zero rowsum (16384 floats)
        float4* rz = (float4*)g_rowsum;
        for (int i = tid; i < 4096; i += 128) rz[i] = make_float4(0, 0, 0, 0);
        // zero all counters
        for (int i = tid; i < 128; i += 128) g_cntQK[i] = 0u;
        for (int i = tid; i < 128; i += 128) g_cntS[i] = 0u;
        if (tid < 32) g_cntV[tid] = 0u;
        if (tid < B_) g_cnt_x[tid] = 0u;
        if (tid == 0) { g_cnt_w = 0u; g_cnt_done = 0u; }
    }
}

// ===========================================================================
extern "C" void kernel_launch(void* const* d_in, const int* in_sizes, int n_in,
                              void* d_out, int out_size)
{
    const float* x  = (const float*)d_in[0];
    const float* Wq = (const float*)d_in[1];
    const float* bq = (const float*)d_in[2];
    const float* Wk = (const float*)d_in[3];
    const float* bk = (const float*)d_in[4];
    const float* Wv = (const float*)d_in[5];
    const float* bv = (const float*)d_in[6];
    float* out = (float*)d_out;

    cudaFuncSetAttribute(megakernel, cudaFuncAttributeMaxDynamicSharedMemorySize, SMEMB);

    // whole pipeline: prep -> proj -> scores -> AV -> reset, one launch
    megakernel<<<12290, 128, SMEMB>>>(x, Wq, bq, Wk, bk, Wv, bv, out);
}